// round 13
// baseline (speedup 1.0000x reference)
#include <cuda_runtime.h>
#include <cuda_fp16.h>
#include <math.h>
#include <stdint.h>

// Problem constants
#define BATCH 2
#define SEQ   2048
#define EMB   1024
#define NH    16
#define HD    64
#define FFD   4096
#define MTOK  (BATCH*SEQ)     // 4096
#define QKV_N (3*EMB)         // 3072
#define LN_EPS 1e-5f

// Scratch (device globals; allocations are forbidden in kernel_launch).
__device__ __half g_qkv[MTOK*QKV_N];     // fp16 QKV (attention input)
__device__ float  g_x2 [MTOK*EMB];       // fp32 residual-1
__device__ __half g_xn [MTOK*EMB];       // LN out (fp16), reused for LN2
__device__ __half g_att[MTOK*EMB];       // attention out (fp16)
__device__ __half g_h  [MTOK*FFD];       // FFN1 out (fp16)
__device__ __half g_wqkv[EMB*QKV_N];     // fp16 weights
__device__ __half g_wout[EMB*EMB];
__device__ __half g_w1  [EMB*FFD];
__device__ __half g_w2  [FFD*EMB];

// ---------------------------------------------------------------------------
// helpers
// ---------------------------------------------------------------------------
__device__ __forceinline__ uint32_t pack2h(float lo, float hi)
{
    uint32_t r;
    asm("cvt.rn.f16x2.f32 %0, %1, %2;" : "=r"(r) : "f"(hi), "f"(lo));
    return r;
}
__device__ __forceinline__ void mma_f16(float* d, const uint32_t* a, const uint32_t* b)
{
    asm volatile(
        "mma.sync.aligned.m16n8k16.row.col.f32.f16.f16.f32 "
        "{%0,%1,%2,%3}, {%4,%5,%6,%7}, {%8,%9}, {%0,%1,%2,%3};\n"
        : "+f"(d[0]), "+f"(d[1]), "+f"(d[2]), "+f"(d[3])
        : "r"(a[0]), "r"(a[1]), "r"(a[2]), "r"(a[3]), "r"(b[0]), "r"(b[1]));
}
__device__ __forceinline__ void ldsm4(uint32_t* r, uint32_t addr)
{
    asm volatile("ldmatrix.sync.aligned.m8n8.x4.shared.b16 {%0,%1,%2,%3}, [%4];"
                 : "=r"(r[0]), "=r"(r[1]), "=r"(r[2]), "=r"(r[3]) : "r"(addr));
}
__device__ __forceinline__ void ldsm4t(uint32_t* r, uint32_t addr)
{
    asm volatile("ldmatrix.sync.aligned.m8n8.x4.trans.shared.b16 {%0,%1,%2,%3}, [%4];"
                 : "=r"(r[0]), "=r"(r[1]), "=r"(r[2]), "=r"(r[3]) : "r"(addr));
}
__device__ __forceinline__ void cpa16(uint32_t dst, const void* src)
{
    asm volatile("cp.async.ca.shared.global [%0], [%1], 16;" :: "r"(dst), "l"(src));
}
#define CP_COMMIT() asm volatile("cp.async.commit_group;")
#define CP_WAIT1()  asm volatile("cp.async.wait_group 1;")

// ---------------------------------------------------------------------------
// fp32 -> fp16 conversion (weights), 8 elems/thread
// ---------------------------------------------------------------------------
__global__ __launch_bounds__(256) void cvt_h(const float* __restrict__ src,
                                             __half* __restrict__ dst, int n)
{
    int i = (blockIdx.x * 256 + threadIdx.x) * 8;
    if (i >= n) return;
    float4 f0 = *(const float4*)&src[i];
    float4 f1 = *(const float4*)&src[i + 4];
    uint4 u;
    u.x = pack2h(f0.x, f0.y); u.y = pack2h(f0.z, f0.w);
    u.z = pack2h(f1.x, f1.y); u.w = pack2h(f1.z, f1.w);
    *(uint4*)&dst[i] = u;
}

// ---------------------------------------------------------------------------
// LayerNorm, fp16 output
// ---------------------------------------------------------------------------
__global__ __launch_bounds__(256) void ln_h(const float* __restrict__ x,
                                            const float* __restrict__ g,
                                            const float* __restrict__ b,
                                            __half* __restrict__ out)
{
    int row = blockIdx.x;
    const float* xr = x + (size_t)row * EMB;
    float v[4];
    float sum = 0.f, sq = 0.f;
#pragma unroll
    for (int i = 0; i < 4; i++) {
        v[i] = xr[threadIdx.x + i * 256];
        sum += v[i];
        sq  += v[i] * v[i];
    }
#pragma unroll
    for (int o = 16; o > 0; o >>= 1) {
        sum += __shfl_xor_sync(0xffffffffu, sum, o);
        sq  += __shfl_xor_sync(0xffffffffu, sq,  o);
    }
    __shared__ float s1[8], s2[8];
    int w = threadIdx.x >> 5, l = threadIdx.x & 31;
    if (l == 0) { s1[w] = sum; s2[w] = sq; }
    __syncthreads();
    sum = 0.f; sq = 0.f;
#pragma unroll
    for (int i = 0; i < 8; i++) { sum += s1[i]; sq += s2[i]; }
    float mu  = sum * (1.0f / EMB);
    float var = sq * (1.0f / EMB) - mu * mu;
    float inv = rsqrtf(var + LN_EPS);
    __half* orow = out + (size_t)row * EMB;
#pragma unroll
    for (int i = 0; i < 4; i++) {
        int c = threadIdx.x + i * 256;
        orow[c] = __float2half((v[i] - mu) * inv * g[c] + b[c]);
    }
}

// ---------------------------------------------------------------------------
// fp16 async-pipelined tensor-core GEMM, 128x256 CTA tile.
// 8 warps (2 x 4), warp tile 64x64, mma.m16n8k16, 2-stage cp.async
// pipeline (48KB static smem), ldmatrix fragment loads, XOR-swizzled smem.
// One cp.async group is committed EVERY iteration (empty on the last) so
// that wait_group 1 at iteration t always retires group t (the stage being
// computed) — the missing final commit in R12 raced the last k-tile.
// A[M,K], B[K,N] row-major fp16.
// EPI: 0 ->fp32 C; 1 ->fp32 C +bias+res; 2 ->fp16 C +bias+GELU; 3 ->fp16 C.
// Requires M%128==0, N%256==0, K%32==0.
// ---------------------------------------------------------------------------
template <int EPI>
__global__ __launch_bounds__(256) void gemm256(const __half* __restrict__ A,
                                               const __half* __restrict__ B,
                                               void* __restrict__ Cv,
                                               const float* __restrict__ bias,
                                               const float* __restrict__ res,
                                               int M, int N, int K)
{
    __shared__ __half As[2][128][32];    // 8KB/stage, swizzle chunk^((row>>1)&3)
    __shared__ __half Bs[2][32][256];    // 16KB/stage, swizzle chunk^(row&7) (low 3 bits)

    const int tid = threadIdx.x;
    const int m0 = blockIdx.y * 128;
    const int n0 = blockIdx.x * 256;

    const int warpId = tid >> 5;
    const int lane   = tid & 31;
    const int wm = (warpId & 1) * 64;
    const int wn = (warpId >> 1) * 64;
    const int g  = lane >> 2;
    const int t3 = lane & 3;

    const uint32_t aSm = (uint32_t)__cvta_generic_to_shared(&As[0][0][0]);
    const uint32_t bSm = (uint32_t)__cvta_generic_to_shared(&Bs[0][0][0]);

    const int lrow = lane & 15;
    const int csel = lane >> 4;

    // fill mappings: A 2 x 16B, B 4 x 16B per thread per stage
    const int fAr = tid >> 2, fAc = tid & 3;
    const int fBk = tid >> 3, fBc = tid & 7;

    const int T = K >> 5;

    float acc[4][8][4];
#pragma unroll
    for (int i = 0; i < 4; i++)
#pragma unroll
        for (int j = 0; j < 8; j++)
#pragma unroll
            for (int c = 0; c < 4; c++) acc[i][j][c] = 0.f;

#define FILL(st, kt)                                                            \
    do {                                                                        \
        int r0_ = fAr, r1_ = fAr + 64;                                          \
        cpa16(aSm + (st)*8192 + r0_*64 + ((fAc ^ ((r0_>>1)&3))<<4),             \
              A + (size_t)(m0 + r0_) * K + (kt)*32 + fAc*8);                    \
        cpa16(aSm + (st)*8192 + r1_*64 + ((fAc ^ ((r1_>>1)&3))<<4),             \
              A + (size_t)(m0 + r1_) * K + (kt)*32 + fAc*8);                    \
        _Pragma("unroll")                                                       \
        for (int j_ = 0; j_ < 4; j_++) {                                        \
            int ch_ = fBc + 8 * j_;                                             \
            cpa16(bSm + (st)*16384 + fBk*512 + ((ch_ ^ (fBk&7))<<4),            \
                  B + (size_t)((kt)*32 + fBk) * N + n0 + ch_*8);                \
        }                                                                       \
    } while (0)

    FILL(0, 0); CP_COMMIT();   // group 0

    for (int t = 0; t < T; t++) {
        if (t + 1 < T) FILL((t + 1) & 1, t + 1);
        CP_COMMIT();           // group t+1 (empty on last iteration)
        CP_WAIT1();            // retires groups 0..t  -> stage t landed
        __syncthreads();
        const int st = t & 1;
        const uint32_t aStage = aSm + st * 8192;
        const uint32_t bStage = bSm + st * 16384;

#pragma unroll
        for (int kb = 0; kb < 2; kb++) {
            uint32_t af[4][4];
#pragma unroll
            for (int mi = 0; mi < 4; mi++) {
                int row = wm + mi * 16 + lrow;
                uint32_t ad = aStage + row * 64
                            + ((((kb << 1) | csel) ^ ((row >> 1) & 3)) << 4);
                ldsm4(af[mi], ad);
            }
            uint32_t bfr[4][4];
#pragma unroll
            for (int p = 0; p < 4; p++) {
                int krow = kb * 16 + lrow;
                int nch  = (wn >> 3) + p * 2 + csel;
                uint32_t bd = bStage + krow * 512 + ((nch ^ (krow & 7)) << 4);
                ldsm4t(bfr[p], bd);
            }
#pragma unroll
            for (int mi = 0; mi < 4; mi++)
#pragma unroll
                for (int ni = 0; ni < 8; ni++)
                    mma_f16(acc[mi][ni], af[mi], &bfr[ni >> 1][(ni & 1) * 2]);
        }
        __syncthreads();       // compute done before next FILL overwrites st
    }
#undef FILL

    // Epilogue: c0,c1 at (row, 2*t3+{0,1}); c2,c3 at (row+8, same cols)
#pragma unroll
    for (int mi = 0; mi < 4; mi++) {
#pragma unroll
        for (int rr = 0; rr < 2; rr++) {
            int row = m0 + wm + mi * 16 + g + rr * 8;
#pragma unroll
            for (int ni = 0; ni < 8; ni++) {
                int col = n0 + wn + ni * 8 + 2 * t3;
                float v0 = acc[mi][ni][rr * 2 + 0];
                float v1 = acc[mi][ni][rr * 2 + 1];
                if (EPI == 1 || EPI == 2) { v0 += bias[col]; v1 += bias[col + 1]; }
                if (EPI == 1) {
                    const float* Rp = res + (size_t)row * N + col;
                    v0 += Rp[0]; v1 += Rp[1];
                    float* C = (float*)Cv;
                    *(float2*)&C[(size_t)row * N + col] = make_float2(v0, v1);
                } else if (EPI == 2) {
                    v0 = 0.5f * v0 * (1.0f + erff(v0 * 0.70710678118654752f));
                    v1 = 0.5f * v1 * (1.0f + erff(v1 * 0.70710678118654752f));
                    uint32_t* Ch = (uint32_t*)Cv;
                    Ch[((size_t)row * N + col) >> 1] = pack2h(v0, v1);
                } else if (EPI == 3) {
                    uint32_t* Ch = (uint32_t*)Cv;
                    Ch[((size_t)row * N + col) >> 1] = pack2h(v0, v1);
                } else {
                    float* C = (float*)Cv;
                    *(float2*)&C[(size_t)row * N + col] = make_float2(v0, v1);
                }
            }
        }
    }
}

// ---------------------------------------------------------------------------
// fp16 tensor-core flash attention (validated R11).
// grid=(SEQ/64, NH, BATCH), 128 threads (4 warps).
// ---------------------------------------------------------------------------
__global__ __launch_bounds__(128) void attn_h16(const __half* __restrict__ qkv,
                                                __half* __restrict__ out)
{
    __shared__ __half Ks[64][72];   // K tile (rows=token, cols=d); reused as P
    __shared__ __half Vs[64][72];   // V tile (rows=token, cols=d)

    const int qb = blockIdx.x;
    const int h  = blockIdx.y;
    const int b  = blockIdx.z;
    const int tid  = threadIdx.x;
    const int w    = tid >> 5;
    const int lane = tid & 31;
    const int g  = lane >> 2;
    const int t3 = lane & 3;
    const int lrow = lane & 15;
    const int csel = lane >> 4;

    const float SCL = 2.8284271247461903f;  // 64^0.25 applied to logits
    const __half* base = qkv + (size_t)b * SEQ * QKV_N + h * HD;
    const uint32_t vSm = (uint32_t)__cvta_generic_to_shared(&Vs[0][0]);

    const int qr0 = qb * 64 + w * 16 + g;
    const __half* q0 = base + (size_t)qr0 * QKV_N;
    const __half* q8 = q0 + (size_t)8 * QKV_N;

    uint32_t qf[4][4];
#pragma unroll
    for (int kc = 0; kc < 4; kc++) {
        qf[kc][0] = *(const uint32_t*)&q0[kc * 16 + 2 * t3];
        qf[kc][1] = *(const uint32_t*)&q8[kc * 16 + 2 * t3];
        qf[kc][2] = *(const uint32_t*)&q0[kc * 16 + 2 * t3 + 8];
        qf[kc][3] = *(const uint32_t*)&q8[kc * 16 + 2 * t3 + 8];
    }

    float oacc[8][4];
#pragma unroll
    for (int i = 0; i < 8; i++)
#pragma unroll
        for (int c = 0; c < 4; c++) oacc[i][c] = 0.f;
    float m0 = -1e30f, m1 = -1e30f, l0 = 0.f, l1 = 0.f;

    for (int kt = 0; kt < SEQ / 64; kt++) {
        __syncthreads();
        for (int i = tid; i < 64 * 8; i += 128) {
            int r = i >> 3, c = (i & 7) * 8;
            const __half* kp = base + EMB + (size_t)(kt * 64 + r) * QKV_N + c;
            *(uint4*)&Ks[r][c] = *(const uint4*)kp;
            *(uint4*)&Vs[r][c] = *(const uint4*)(kp + EMB);
        }
        __syncthreads();

        float sacc[8][4];
#pragma unroll
        for (int i = 0; i < 8; i++)
#pragma unroll
            for (int c = 0; c < 4; c++) sacc[i][c] = 0.f;

#pragma unroll
        for (int kc = 0; kc < 4; kc++) {
#pragma unroll
            for (int ni = 0; ni < 8; ni++) {
                uint32_t bf[2];
                bf[0] = *(const uint32_t*)&Ks[ni * 8 + g][kc * 16 + 2 * t3];
                bf[1] = *(const uint32_t*)&Ks[ni * 8 + g][kc * 16 + 2 * t3 + 8];
                mma_f16(sacc[ni], qf[kc], bf);
            }
        }

        float rm0 = -1e30f, rm1 = -1e30f;
#pragma unroll
        for (int ni = 0; ni < 8; ni++) {
            sacc[ni][0] *= SCL; sacc[ni][1] *= SCL;
            sacc[ni][2] *= SCL; sacc[ni][3] *= SCL;
            rm0 = fmaxf(rm0, fmaxf(sacc[ni][0], sacc[ni][1]));
            rm1 = fmaxf(rm1, fmaxf(sacc[ni][2], sacc[ni][3]));
        }
        rm0 = fmaxf(rm0, __shfl_xor_sync(0xffffffffu, rm0, 1));
        rm0 = fmaxf(rm0, __shfl_xor_sync(0xffffffffu, rm0, 2));
        rm1 = fmaxf(rm1, __shfl_xor_sync(0xffffffffu, rm1, 1));
        rm1 = fmaxf(rm1, __shfl_xor_sync(0xffffffffu, rm1, 2));
        float mn0 = fmaxf(m0, rm0), mn1 = fmaxf(m1, rm1);
        float cr0 = __expf(m0 - mn0), cr1 = __expf(m1 - mn1);
        float rs0 = 0.f, rs1 = 0.f;
#pragma unroll
        for (int ni = 0; ni < 8; ni++) {
            sacc[ni][0] = __expf(sacc[ni][0] - mn0);
            sacc[ni][1] = __expf(sacc[ni][1] - mn0);
            sacc[ni][2] = __expf(sacc[ni][2] - mn1);
            sacc[ni][3] = __expf(sacc[ni][3] - mn1);
            rs0 += sacc[ni][0] + sacc[ni][1];
            rs1 += sacc[ni][2] + sacc[ni][3];
        }
        rs0 += __shfl_xor_sync(0xffffffffu, rs0, 1);
        rs0 += __shfl_xor_sync(0xffffffffu, rs0, 2);
        rs1 += __shfl_xor_sync(0xffffffffu, rs1, 1);
        rs1 += __shfl_xor_sync(0xffffffffu, rs1, 2);
        l0 = l0 * cr0 + rs0;  m0 = mn0;
        l1 = l1 * cr1 + rs1;  m1 = mn1;
#pragma unroll
        for (int di = 0; di < 8; di++) {
            oacc[di][0] *= cr0; oacc[di][1] *= cr0;
            oacc[di][2] *= cr1; oacc[di][3] *= cr1;
        }

        __syncthreads();
        const int pr = w * 16 + g;
#pragma unroll
        for (int ni = 0; ni < 8; ni++) {
            *(uint32_t*)&Ks[pr    ][ni * 8 + 2 * t3] = pack2h(sacc[ni][0], sacc[ni][1]);
            *(uint32_t*)&Ks[pr + 8][ni * 8 + 2 * t3] = pack2h(sacc[ni][2], sacc[ni][3]);
        }
        __syncwarp();

#pragma unroll
        for (int kc = 0; kc < 4; kc++) {
            uint32_t pa[4];
            pa[0] = *(const uint32_t*)&Ks[pr    ][kc * 16 + 2 * t3];
            pa[1] = *(const uint32_t*)&Ks[pr + 8][kc * 16 + 2 * t3];
            pa[2] = *(const uint32_t*)&Ks[pr    ][kc * 16 + 2 * t3 + 8];
            pa[3] = *(const uint32_t*)&Ks[pr + 8][kc * 16 + 2 * t3 + 8];

            uint32_t bfr[4][4];
#pragma unroll
            for (int p = 0; p < 4; p++) {
                int tok = kc * 16 + lrow;
                uint32_t bd = vSm + tok * 144 + (p * 2 + csel) * 16;
                ldsm4t(bfr[p], bd);
            }
#pragma unroll
            for (int di = 0; di < 8; di++)
                mma_f16(oacc[di], pa, &bfr[di >> 1][(di & 1) * 2]);
        }
    }

    float inv0 = 1.0f / l0, inv1 = 1.0f / l1;
    __half* o0 = out + (size_t)(b * SEQ + qr0) * EMB + h * HD;
    __half* o8 = o0 + (size_t)8 * EMB;
#pragma unroll
    for (int di = 0; di < 8; di++) {
        int col = di * 8 + 2 * t3;
        *(uint32_t*)&o0[col] = pack2h(oacc[di][0] * inv0, oacc[di][1] * inv0);
        *(uint32_t*)&o8[col] = pack2h(oacc[di][2] * inv1, oacc[di][3] * inv1);
    }
}

// ---------------------------------------------------------------------------
// Launch
// ---------------------------------------------------------------------------
extern "C" void kernel_launch(void* const* d_in, const int* in_sizes, int n_in,
                              void* d_out, int out_size)
{
    const float* x     = (const float*)d_in[0];
    const float* w_qkv = (const float*)d_in[1];
    const float* w_out = (const float*)d_in[2];
    const float* b_out = (const float*)d_in[3];
    const float* ln1_g = (const float*)d_in[4];
    const float* ln1_b = (const float*)d_in[5];
    const float* ln2_g = (const float*)d_in[6];
    const float* ln2_b = (const float*)d_in[7];
    const float* w1    = (const float*)d_in[8];
    const float* b1    = (const float*)d_in[9];
    const float* w2    = (const float*)d_in[10];
    const float* b2    = (const float*)d_in[11];
    float* out = (float*)d_out;

    float  *p_x2;
    __half *p_qkv, *p_xn, *p_att, *p_h, *p_wqkv, *p_wout, *p_w1, *p_w2;
    cudaGetSymbolAddress((void**)&p_qkv,  g_qkv);
    cudaGetSymbolAddress((void**)&p_x2,   g_x2);
    cudaGetSymbolAddress((void**)&p_xn,   g_xn);
    cudaGetSymbolAddress((void**)&p_att,  g_att);
    cudaGetSymbolAddress((void**)&p_h,    g_h);
    cudaGetSymbolAddress((void**)&p_wqkv, g_wqkv);
    cudaGetSymbolAddress((void**)&p_wout, g_wout);
    cudaGetSymbolAddress((void**)&p_w1,   g_w1);
    cudaGetSymbolAddress((void**)&p_w2,   g_w2);

    // 0. weight conversions (fp32 -> fp16)
    cvt_h<<<(EMB*QKV_N)/2048, 256>>>(w_qkv, p_wqkv, EMB*QKV_N);
    cvt_h<<<(EMB*EMB)/2048,  256>>>(w_out, p_wout, EMB*EMB);
    cvt_h<<<(EMB*FFD)/2048,  256>>>(w1,    p_w1,   EMB*FFD);
    cvt_h<<<(FFD*EMB)/2048,  256>>>(w2,    p_w2,   FFD*EMB);

    // 1. LN1 -> fp16
    ln_h<<<MTOK, 256>>>(x, ln1_g, ln1_b, p_xn);
    // 2. QKV GEMM -> fp16
    gemm256<3><<<dim3(QKV_N / 256, MTOK / 128), 256>>>(p_xn, p_wqkv, p_qkv,
                                                       nullptr, nullptr,
                                                       MTOK, QKV_N, EMB);
    // 3. Attention (fp16 tensor-core) -> fp16
    attn_h16<<<dim3(SEQ / 64, NH, BATCH), 128>>>(p_qkv, p_att);
    // 4. Output projection + bias + residual(x) -> fp32
    gemm256<1><<<dim3(EMB / 256, MTOK / 128), 256>>>(p_att, p_wout, p_x2,
                                                     b_out, x,
                                                     MTOK, EMB, EMB);
    // 5. LN2 -> fp16
    ln_h<<<MTOK, 256>>>(p_x2, ln2_g, ln2_b, p_xn);
    // 6. FFN1 + bias + GELU -> fp16
    gemm256<2><<<dim3(FFD / 256, MTOK / 128), 256>>>(p_xn, p_w1, p_h,
                                                     b1, nullptr,
                                                     MTOK, FFD, EMB);
    // 7. FFN2 + bias + residual(x2) -> out (fp32)
    gemm256<1><<<dim3(EMB / 256, MTOK / 128), 256>>>(p_h, p_w2, out,
                                                     b2, p_x2,
                                                     MTOK, EMB, FFD);
}

// round 17
// speedup vs baseline: 1.1057x; 1.1057x over previous
#include <cuda_runtime.h>
#include <cuda_fp16.h>
#include <math.h>
#include <stdint.h>

// Problem constants
#define BATCH 2
#define SEQ   2048
#define EMB   1024
#define NH    16
#define HD    64
#define FFD   4096
#define MTOK  (BATCH*SEQ)     // 4096
#define QKV_N (3*EMB)         // 3072
#define LN_EPS 1e-5f

// Scratch (device globals; allocations are forbidden in kernel_launch).
__device__ __half g_qkv[MTOK*QKV_N];     // fp16 QKV (attention input)
__device__ float  g_x2 [MTOK*EMB];       // fp32 residual-1
__device__ __half g_xn [MTOK*EMB];       // LN out (fp16), reused for LN2
__device__ __half g_att[MTOK*EMB];       // attention out (fp16)
__device__ __half g_h  [MTOK*FFD];       // FFN1 out (fp16)
__device__ __half g_wqkv[EMB*QKV_N];     // fp16 weights
__device__ __half g_wout[EMB*EMB];
__device__ __half g_w1  [EMB*FFD];
__device__ __half g_w2  [FFD*EMB];

// ---------------------------------------------------------------------------
// helpers
// ---------------------------------------------------------------------------
__device__ __forceinline__ uint32_t pack2h(float lo, float hi)
{
    uint32_t r;
    asm("cvt.rn.f16x2.f32 %0, %1, %2;" : "=r"(r) : "f"(hi), "f"(lo));
    return r;
}
__device__ __forceinline__ void mma_f16(float* d, const uint32_t* a, const uint32_t* b)
{
    asm volatile(
        "mma.sync.aligned.m16n8k16.row.col.f32.f16.f16.f32 "
        "{%0,%1,%2,%3}, {%4,%5,%6,%7}, {%8,%9}, {%0,%1,%2,%3};\n"
        : "+f"(d[0]), "+f"(d[1]), "+f"(d[2]), "+f"(d[3])
        : "r"(a[0]), "r"(a[1]), "r"(a[2]), "r"(a[3]), "r"(b[0]), "r"(b[1]));
}
__device__ __forceinline__ void ldsm4(uint32_t* r, uint32_t addr)
{
    asm volatile("ldmatrix.sync.aligned.m8n8.x4.shared.b16 {%0,%1,%2,%3}, [%4];"
                 : "=r"(r[0]), "=r"(r[1]), "=r"(r[2]), "=r"(r[3]) : "r"(addr));
}
__device__ __forceinline__ void ldsm4t(uint32_t* r, uint32_t addr)
{
    asm volatile("ldmatrix.sync.aligned.m8n8.x4.trans.shared.b16 {%0,%1,%2,%3}, [%4];"
                 : "=r"(r[0]), "=r"(r[1]), "=r"(r[2]), "=r"(r[3]) : "r"(addr));
}
__device__ __forceinline__ void cpa16(uint32_t dst, const void* src)
{
    asm volatile("cp.async.ca.shared.global [%0], [%1], 16;" :: "r"(dst), "l"(src));
}
#define CP_COMMIT() asm volatile("cp.async.commit_group;")
#define CP_WAIT1()  asm volatile("cp.async.wait_group 1;")

// ---------------------------------------------------------------------------
// fp32 -> fp16 conversion (weights), 8 elems/thread
// ---------------------------------------------------------------------------
__global__ __launch_bounds__(256) void cvt_h(const float* __restrict__ src,
                                             __half* __restrict__ dst, int n)
{
    int i = (blockIdx.x * 256 + threadIdx.x) * 8;
    if (i >= n) return;
    float4 f0 = *(const float4*)&src[i];
    float4 f1 = *(const float4*)&src[i + 4];
    uint4 u;
    u.x = pack2h(f0.x, f0.y); u.y = pack2h(f0.z, f0.w);
    u.z = pack2h(f1.x, f1.y); u.w = pack2h(f1.z, f1.w);
    *(uint4*)&dst[i] = u;
}

// ---------------------------------------------------------------------------
// LayerNorm, fp16 output
// ---------------------------------------------------------------------------
__global__ __launch_bounds__(256) void ln_h(const float* __restrict__ x,
                                            const float* __restrict__ g,
                                            const float* __restrict__ b,
                                            __half* __restrict__ out)
{
    int row = blockIdx.x;
    const float* xr = x + (size_t)row * EMB;
    float v[4];
    float sum = 0.f, sq = 0.f;
#pragma unroll
    for (int i = 0; i < 4; i++) {
        v[i] = xr[threadIdx.x + i * 256];
        sum += v[i];
        sq  += v[i] * v[i];
    }
#pragma unroll
    for (int o = 16; o > 0; o >>= 1) {
        sum += __shfl_xor_sync(0xffffffffu, sum, o);
        sq  += __shfl_xor_sync(0xffffffffu, sq,  o);
    }
    __shared__ float s1[8], s2[8];
    int w = threadIdx.x >> 5, l = threadIdx.x & 31;
    if (l == 0) { s1[w] = sum; s2[w] = sq; }
    __syncthreads();
    sum = 0.f; sq = 0.f;
#pragma unroll
    for (int i = 0; i < 8; i++) { sum += s1[i]; sq += s2[i]; }
    float mu  = sum * (1.0f / EMB);
    float var = sq * (1.0f / EMB) - mu * mu;
    float inv = rsqrtf(var + LN_EPS);
    __half* orow = out + (size_t)row * EMB;
#pragma unroll
    for (int i = 0; i < 4; i++) {
        int c = threadIdx.x + i * 256;
        orow[c] = __float2half((v[i] - mu) * inv * g[c] + b[c]);
    }
}

// ---------------------------------------------------------------------------
// fp16 async-pipelined tensor-core GEMM (validated R9/R11).
// 128x128x32 CTA tile, 8 warps (2x4), warp tile 64x32, mma.m16n8k16,
// 3-stage cp.async pipeline, ldmatrix fragment loads, XOR-swizzled smem.
// EPI: 0 ->fp32 C; 1 ->fp32 C +bias+res; 2 ->fp16 C +bias+GELU; 3 ->fp16 C.
// ---------------------------------------------------------------------------
template <int EPI>
__global__ __launch_bounds__(256, 2) void gemm16(const __half* __restrict__ A,
                                                 const __half* __restrict__ B,
                                                 void* __restrict__ Cv,
                                                 const float* __restrict__ bias,
                                                 const float* __restrict__ res,
                                                 int M, int N, int K)
{
    __shared__ __half As[3][128][32];   // 8KB/stage, swizzle chunk^((row>>1)&3)
    __shared__ __half Bs[3][32][128];   // 8KB/stage, swizzle chunk^(row&7)

    const int tid = threadIdx.x;
    const int m0 = blockIdx.y * 128;
    const int n0 = blockIdx.x * 128;

    const int warpId = tid >> 5;
    const int lane   = tid & 31;
    const int wm = (warpId & 1) * 64;
    const int wn = (warpId >> 1) * 32;
    const int g  = lane >> 2;
    const int t3 = lane & 3;

    const uint32_t aSm = (uint32_t)__cvta_generic_to_shared(&As[0][0][0]);
    const uint32_t bSm = (uint32_t)__cvta_generic_to_shared(&Bs[0][0][0]);

    const int lrow = lane & 15;
    const int csel = lane >> 4;

    const int fAr = tid >> 2, fAc = tid & 3;
    const int fBk = tid >> 4, fBc = tid & 15;

    const int T = K >> 5;

    float acc[4][4][4];
#pragma unroll
    for (int i = 0; i < 4; i++)
#pragma unroll
        for (int j = 0; j < 4; j++)
#pragma unroll
            for (int c = 0; c < 4; c++) acc[i][j][c] = 0.f;

#define FILL(st, kt)                                                            \
    do {                                                                        \
        int r0_ = fAr, r1_ = fAr + 64;                                          \
        cpa16(aSm + (st)*8192 + r0_*64 + ((fAc ^ ((r0_>>1)&3))<<4),             \
              A + (size_t)(m0 + r0_) * K + (kt)*32 + fAc*8);                    \
        cpa16(aSm + (st)*8192 + r1_*64 + ((fAc ^ ((r1_>>1)&3))<<4),             \
              A + (size_t)(m0 + r1_) * K + (kt)*32 + fAc*8);                    \
        int k0_ = fBk, k1_ = fBk + 16;                                          \
        cpa16(bSm + (st)*8192 + k0_*256 + ((fBc ^ (k0_&7))<<4),                 \
              B + (size_t)((kt)*32 + k0_) * N + n0 + fBc*8);                    \
        cpa16(bSm + (st)*8192 + k1_*256 + ((fBc ^ (k1_&7))<<4),                 \
              B + (size_t)((kt)*32 + k1_) * N + n0 + fBc*8);                    \
    } while (0)

    FILL(0, 0); CP_COMMIT();
    FILL(1, 1); CP_COMMIT();

    for (int t = 0; t < T; t++) {
        CP_WAIT1();
        __syncthreads();
        const int st = t % 3;
        const uint32_t aStage = aSm + st * 8192;
        const uint32_t bStage = bSm + st * 8192;

#pragma unroll
        for (int kb = 0; kb < 2; kb++) {
            uint32_t af[4][4];
#pragma unroll
            for (int mi = 0; mi < 4; mi++) {
                int row = wm + mi * 16 + lrow;
                uint32_t ad = aStage + row * 64
                            + ((((kb << 1) | csel) ^ ((row >> 1) & 3)) << 4);
                ldsm4(af[mi], ad);
            }
            uint32_t bfr[2][4];
#pragma unroll
            for (int p = 0; p < 2; p++) {
                int krow = kb * 16 + lrow;
                int nch  = (wn >> 3) + p * 2 + csel;
                uint32_t bd = bStage + krow * 256 + ((nch ^ (krow & 7)) << 4);
                ldsm4t(bfr[p], bd);
            }
#pragma unroll
            for (int mi = 0; mi < 4; mi++)
#pragma unroll
                for (int ni = 0; ni < 4; ni++)
                    mma_f16(acc[mi][ni], af[mi], &bfr[ni >> 1][(ni & 1) * 2]);
        }

        if (t + 2 < T) FILL((t + 2) % 3, t + 2);
        CP_COMMIT();
    }
#undef FILL

#pragma unroll
    for (int mi = 0; mi < 4; mi++) {
#pragma unroll
        for (int rr = 0; rr < 2; rr++) {
            int row = m0 + wm + mi * 16 + g + rr * 8;
#pragma unroll
            for (int ni = 0; ni < 4; ni++) {
                int col = n0 + wn + ni * 8 + 2 * t3;
                float v0 = acc[mi][ni][rr * 2 + 0];
                float v1 = acc[mi][ni][rr * 2 + 1];
                if (EPI == 1 || EPI == 2) { v0 += bias[col]; v1 += bias[col + 1]; }
                if (EPI == 1) {
                    const float* Rp = res + (size_t)row * N + col;
                    v0 += Rp[0]; v1 += Rp[1];
                    float* C = (float*)Cv;
                    *(float2*)&C[(size_t)row * N + col] = make_float2(v0, v1);
                } else if (EPI == 2) {
                    v0 = 0.5f * v0 * (1.0f + erff(v0 * 0.70710678118654752f));
                    v1 = 0.5f * v1 * (1.0f + erff(v1 * 0.70710678118654752f));
                    uint32_t* Ch = (uint32_t*)Cv;
                    Ch[((size_t)row * N + col) >> 1] = pack2h(v0, v1);
                } else if (EPI == 3) {
                    uint32_t* Ch = (uint32_t*)Cv;
                    Ch[((size_t)row * N + col) >> 1] = pack2h(v0, v1);
                } else {
                    float* C = (float*)Cv;
                    *(float2*)&C[(size_t)row * N + col] = make_float2(v0, v1);
                }
            }
        }
    }
}

// ---------------------------------------------------------------------------
// fp16 tensor-core flash attention, 128-q-row CTA.
// grid=(SEQ/128, NH, BATCH), 256 threads (8 warps, each owns 16 q-rows).
// Same per-warp math as the validated R11 kernel; K/V tiles (64x64) are now
// shared by 8 warps (2x the reuse, half the global K/V traffic), and P gets
// a dedicated buffer (no Ks aliasing -> one fewer sync per tile).
// ---------------------------------------------------------------------------
__global__ __launch_bounds__(256) void attn_h16(const __half* __restrict__ qkv,
                                                __half* __restrict__ out)
{
    __shared__ __half Ks[64][72];    // K tile (rows=token, cols=d)
    __shared__ __half Vs[64][72];    // V tile (rows=token, cols=d)
    __shared__ __half Ps[128][72];   // P tile (rows=q, cols=token)

    const int qb = blockIdx.x;
    const int h  = blockIdx.y;
    const int b  = blockIdx.z;
    const int tid  = threadIdx.x;
    const int w    = tid >> 5;
    const int lane = tid & 31;
    const int g  = lane >> 2;
    const int t3 = lane & 3;
    const int lrow = lane & 15;
    const int csel = lane >> 4;

    const float SCL = 2.8284271247461903f;  // 64^0.25 applied to logits
    const __half* base = qkv + (size_t)b * SEQ * QKV_N + h * HD;
    const uint32_t vSm = (uint32_t)__cvta_generic_to_shared(&Vs[0][0]);

    const int qr0 = qb * 128 + w * 16 + g;
    const __half* q0 = base + (size_t)qr0 * QKV_N;
    const __half* q8 = q0 + (size_t)8 * QKV_N;

    uint32_t qf[4][4];
#pragma unroll
    for (int kc = 0; kc < 4; kc++) {
        qf[kc][0] = *(const uint32_t*)&q0[kc * 16 + 2 * t3];
        qf[kc][1] = *(const uint32_t*)&q8[kc * 16 + 2 * t3];
        qf[kc][2] = *(const uint32_t*)&q0[kc * 16 + 2 * t3 + 8];
        qf[kc][3] = *(const uint32_t*)&q8[kc * 16 + 2 * t3 + 8];
    }

    float oacc[8][4];
#pragma unroll
    for (int i = 0; i < 8; i++)
#pragma unroll
        for (int c = 0; c < 4; c++) oacc[i][c] = 0.f;
    float m0 = -1e30f, m1 = -1e30f, l0 = 0.f, l1 = 0.f;

    for (int kt = 0; kt < SEQ / 64; kt++) {
        __syncthreads();   // previous tile's Ks/Vs reads complete
        for (int i = tid; i < 64 * 8; i += 256) {
            int r = i >> 3, c = (i & 7) * 8;
            const __half* kp = base + EMB + (size_t)(kt * 64 + r) * QKV_N + c;
            *(uint4*)&Ks[r][c] = *(const uint4*)kp;
            *(uint4*)&Vs[r][c] = *(const uint4*)(kp + EMB);
        }
        __syncthreads();

        // S = Q.K^T (warp: 16 x 64), fp32 accumulate
        float sacc[8][4];
#pragma unroll
        for (int i = 0; i < 8; i++)
#pragma unroll
            for (int c = 0; c < 4; c++) sacc[i][c] = 0.f;

#pragma unroll
        for (int kc = 0; kc < 4; kc++) {
#pragma unroll
            for (int ni = 0; ni < 8; ni++) {
                uint32_t bf[2];
                bf[0] = *(const uint32_t*)&Ks[ni * 8 + g][kc * 16 + 2 * t3];
                bf[1] = *(const uint32_t*)&Ks[ni * 8 + g][kc * 16 + 2 * t3 + 8];
                mma_f16(sacc[ni], qf[kc], bf);
            }
        }

        // Scale logits, online softmax (rows g / g+8, 4-lane shfl reduce)
        float rm0 = -1e30f, rm1 = -1e30f;
#pragma unroll
        for (int ni = 0; ni < 8; ni++) {
            sacc[ni][0] *= SCL; sacc[ni][1] *= SCL;
            sacc[ni][2] *= SCL; sacc[ni][3] *= SCL;
            rm0 = fmaxf(rm0, fmaxf(sacc[ni][0], sacc[ni][1]));
            rm1 = fmaxf(rm1, fmaxf(sacc[ni][2], sacc[ni][3]));
        }
        rm0 = fmaxf(rm0, __shfl_xor_sync(0xffffffffu, rm0, 1));
        rm0 = fmaxf(rm0, __shfl_xor_sync(0xffffffffu, rm0, 2));
        rm1 = fmaxf(rm1, __shfl_xor_sync(0xffffffffu, rm1, 1));
        rm1 = fmaxf(rm1, __shfl_xor_sync(0xffffffffu, rm1, 2));
        float mn0 = fmaxf(m0, rm0), mn1 = fmaxf(m1, rm1);
        float cr0 = __expf(m0 - mn0), cr1 = __expf(m1 - mn1);
        float rs0 = 0.f, rs1 = 0.f;
#pragma unroll
        for (int ni = 0; ni < 8; ni++) {
            sacc[ni][0] = __expf(sacc[ni][0] - mn0);
            sacc[ni][1] = __expf(sacc[ni][1] - mn0);
            sacc[ni][2] = __expf(sacc[ni][2] - mn1);
            sacc[ni][3] = __expf(sacc[ni][3] - mn1);
            rs0 += sacc[ni][0] + sacc[ni][1];
            rs1 += sacc[ni][2] + sacc[ni][3];
        }
        rs0 += __shfl_xor_sync(0xffffffffu, rs0, 1);
        rs0 += __shfl_xor_sync(0xffffffffu, rs0, 2);
        rs1 += __shfl_xor_sync(0xffffffffu, rs1, 1);
        rs1 += __shfl_xor_sync(0xffffffffu, rs1, 2);
        l0 = l0 * cr0 + rs0;  m0 = mn0;
        l1 = l1 * cr1 + rs1;  m1 = mn1;
#pragma unroll
        for (int di = 0; di < 8; di++) {
            oacc[di][0] *= cr0; oacc[di][1] *= cr0;
            oacc[di][2] *= cr1; oacc[di][3] *= cr1;
        }

        // Write P (fp16 pairs) into this warp's Ps rows — no cross-warp hazard
        const int pr = w * 16 + g;
#pragma unroll
        for (int ni = 0; ni < 8; ni++) {
            *(uint32_t*)&Ps[pr    ][ni * 8 + 2 * t3] = pack2h(sacc[ni][0], sacc[ni][1]);
            *(uint32_t*)&Ps[pr + 8][ni * 8 + 2 * t3] = pack2h(sacc[ni][2], sacc[ni][3]);
        }
        __syncwarp();

        // O += P.V  (A = P from smem, B = V via ldmatrix.trans)
#pragma unroll
        for (int kc = 0; kc < 4; kc++) {
            uint32_t pa[4];
            pa[0] = *(const uint32_t*)&Ps[pr    ][kc * 16 + 2 * t3];
            pa[1] = *(const uint32_t*)&Ps[pr + 8][kc * 16 + 2 * t3];
            pa[2] = *(const uint32_t*)&Ps[pr    ][kc * 16 + 2 * t3 + 8];
            pa[3] = *(const uint32_t*)&Ps[pr + 8][kc * 16 + 2 * t3 + 8];

            uint32_t bfr[4][4];
#pragma unroll
            for (int p = 0; p < 4; p++) {
                int tok = kc * 16 + lrow;
                uint32_t bd = vSm + tok * 144 + (p * 2 + csel) * 16;
                ldsm4t(bfr[p], bd);
            }
#pragma unroll
            for (int di = 0; di < 8; di++)
                mma_f16(oacc[di], pa, &bfr[di >> 1][(di & 1) * 2]);
        }
    }

    // Normalize and store fp16: out[b, q, h*64 + d]
    float inv0 = 1.0f / l0, inv1 = 1.0f / l1;
    __half* o0 = out + (size_t)(b * SEQ + qr0) * EMB + h * HD;
    __half* o8 = o0 + (size_t)8 * EMB;
#pragma unroll
    for (int di = 0; di < 8; di++) {
        int col = di * 8 + 2 * t3;
        *(uint32_t*)&o0[col] = pack2h(oacc[di][0] * inv0, oacc[di][1] * inv0);
        *(uint32_t*)&o8[col] = pack2h(oacc[di][2] * inv1, oacc[di][3] * inv1);
    }
}

// ---------------------------------------------------------------------------
// Launch
// ---------------------------------------------------------------------------
extern "C" void kernel_launch(void* const* d_in, const int* in_sizes, int n_in,
                              void* d_out, int out_size)
{
    const float* x     = (const float*)d_in[0];
    const float* w_qkv = (const float*)d_in[1];
    const float* w_out = (const float*)d_in[2];
    const float* b_out = (const float*)d_in[3];
    const float* ln1_g = (const float*)d_in[4];
    const float* ln1_b = (const float*)d_in[5];
    const float* ln2_g = (const float*)d_in[6];
    const float* ln2_b = (const float*)d_in[7];
    const float* w1    = (const float*)d_in[8];
    const float* b1    = (const float*)d_in[9];
    const float* w2    = (const float*)d_in[10];
    const float* b2    = (const float*)d_in[11];
    float* out = (float*)d_out;

    float  *p_x2;
    __half *p_qkv, *p_xn, *p_att, *p_h, *p_wqkv, *p_wout, *p_w1, *p_w2;
    cudaGetSymbolAddress((void**)&p_qkv,  g_qkv);
    cudaGetSymbolAddress((void**)&p_x2,   g_x2);
    cudaGetSymbolAddress((void**)&p_xn,   g_xn);
    cudaGetSymbolAddress((void**)&p_att,  g_att);
    cudaGetSymbolAddress((void**)&p_h,    g_h);
    cudaGetSymbolAddress((void**)&p_wqkv, g_wqkv);
    cudaGetSymbolAddress((void**)&p_wout, g_wout);
    cudaGetSymbolAddress((void**)&p_w1,   g_w1);
    cudaGetSymbolAddress((void**)&p_w2,   g_w2);

    // 0. weight conversions (fp32 -> fp16)
    cvt_h<<<(EMB*QKV_N)/2048, 256>>>(w_qkv, p_wqkv, EMB*QKV_N);
    cvt_h<<<(EMB*EMB)/2048,  256>>>(w_out, p_wout, EMB*EMB);
    cvt_h<<<(EMB*FFD)/2048,  256>>>(w1,    p_w1,   EMB*FFD);
    cvt_h<<<(FFD*EMB)/2048,  256>>>(w2,    p_w2,   FFD*EMB);

    // 1. LN1 -> fp16
    ln_h<<<MTOK, 256>>>(x, ln1_g, ln1_b, p_xn);
    // 2. QKV GEMM -> fp16
    gemm16<3><<<dim3(QKV_N / 128, MTOK / 128), 256>>>(p_xn, p_wqkv, p_qkv,
                                                      nullptr, nullptr,
                                                      MTOK, QKV_N, EMB);
    // 3. Attention (fp16 tensor-core, 128-q-row CTAs) -> fp16
    attn_h16<<<dim3(SEQ / 128, NH, BATCH), 256>>>(p_qkv, p_att);
    // 4. Output projection + bias + residual(x) -> fp32
    gemm16<1><<<dim3(EMB / 128, MTOK / 128), 256>>>(p_att, p_wout, p_x2,
                                                    b_out, x,
                                                    MTOK, EMB, EMB);
    // 5. LN2 -> fp16
    ln_h<<<MTOK, 256>>>(p_x2, ln2_g, ln2_b, p_xn);
    // 6. FFN1 + bias + GELU -> fp16
    gemm16<2><<<dim3(FFD / 128, MTOK / 128), 256>>>(p_xn, p_w1, p_h,
                                                    b1, nullptr,
                                                    MTOK, FFD, EMB);
    // 7. FFN2 + bias + residual(x2) -> out (fp32)
    gemm16<1><<<dim3(EMB / 128, MTOK / 128), 256>>>(p_h, p_w2, out,
                                                    b2, p_x2,
                                                    MTOK, EMB, FFD);
}